// round 2
// baseline (speedup 1.0000x reference)
#include <cuda_runtime.h>
#include <math.h>

#define NBATCH 4096
#define TWO_N  8192
#define DIMK   256
// logits = sim / TEMP = sim * 2
#define INV_TEMP 2.0f

// -------- scratch (no allocs allowed -> __device__ globals) --------
__device__ float g_hat[TWO_N * DIMK];   // normalized reps, 8 MB
__device__ float g_rowsum[TWO_N];       // sum_{j!=i} exp(2*sim_ij)
__device__ float g_pos[TWO_N];          // sim(i, partner(i))

// -------- packed f32x2 helpers (sm_100+ only; ptxas never emits these) ----
static __device__ __forceinline__ unsigned long long pk2(float lo, float hi) {
    unsigned long long r;
    asm("mov.b64 %0, {%1, %2};" : "=l"(r) : "f"(lo), "f"(hi));
    return r;
}
static __device__ __forceinline__ unsigned long long ffma2(
    unsigned long long a, unsigned long long b, unsigned long long c) {
    unsigned long long d;
    asm("fma.rn.f32x2 %0, %1, %2, %3;" : "=l"(d) : "l"(a), "l"(b), "l"(c));
    return d;
}
static __device__ __forceinline__ float2 unpk2(unsigned long long v) {
    float2 f;
    asm("mov.b64 {%0, %1}, %2;" : "=f"(f.x), "=f"(f.y) : "l"(v));
    return f;
}

// ---------------- kernel 1: normalize rows into g_hat ----------------
// reps = cat([zjs, zis]); row r<4096 -> zjs[r], else zis[r-4096]
__global__ void ntx_normalize(const float* __restrict__ zis,
                              const float* __restrict__ zjs) {
    int row  = blockIdx.x * 8 + threadIdx.y;
    int lane = threadIdx.x;
    const float* src = (row < NBATCH) ? (zjs + (size_t)row * DIMK)
                                      : (zis + (size_t)(row - NBATCH) * DIMK);
    const float4* s4 = (const float4*)src;
    float4 v0 = s4[lane];
    float4 v1 = s4[lane + 32];
    float ss = v0.x*v0.x + v0.y*v0.y + v0.z*v0.z + v0.w*v0.w
             + v1.x*v1.x + v1.y*v1.y + v1.z*v1.z + v1.w*v1.w;
    #pragma unroll
    for (int off = 16; off >= 1; off >>= 1)
        ss += __shfl_xor_sync(0xFFFFFFFFu, ss, off);
    float rn = rsqrtf(ss);   // norms ~16 >> eps, clamp is dead
    float4* d4 = (float4*)&g_hat[(size_t)row * DIMK];
    v0.x*=rn; v0.y*=rn; v0.z*=rn; v0.w*=rn;
    v1.x*=rn; v1.y*=rn; v1.z*=rn; v1.w*=rn;
    d4[lane]      = v0;
    d4[lane + 32] = v1;
}

// ---------------- kernel 2: positive-pair sims ----------------
__global__ void ntx_pos() {
    int row  = blockIdx.x * 8 + threadIdx.y;
    int par  = (row < NBATCH) ? row + NBATCH : row - NBATCH;
    int lane = threadIdx.x;
    const float4* a = (const float4*)&g_hat[(size_t)row * DIMK];
    const float4* b = (const float4*)&g_hat[(size_t)par * DIMK];
    float4 a0 = a[lane], a1 = a[lane + 32];
    float4 b0 = b[lane], b1 = b[lane + 32];
    float s = a0.x*b0.x + a0.y*b0.y + a0.z*b0.z + a0.w*b0.w
            + a1.x*b1.x + a1.y*b1.y + a1.z*b1.z + a1.w*b1.w;
    #pragma unroll
    for (int off = 16; off >= 1; off >>= 1)
        s += __shfl_xor_sync(0xFFFFFFFFu, s, off);
    if (lane == 0) g_pos[row] = s;
}

// ---------------- kernel 3: fused Gram + exp + row-sum ----------------
// grid = 128 blocks (one wave), each owns 64 rows vs all 8192 cols.
// SMEM: A tile 64x256 fp32 (float4 units, XOR-swizzled) persistent,
//       B tile same, reloaded per 64-col tile. 4x4 micro-tile/thread,
//       K-paired f32x2 accumulation (dot = lo+hi at the end).
__global__ __launch_bounds__(256, 1) void ntx_main() {
    extern __shared__ float4 sm4[];
    float4* Ash = sm4;            // 64 rows * 64 float4
    float4* Bsh = sm4 + 64 * 64;
    __shared__ float s_row[64];

    int tid = threadIdx.x;
    int tx = tid & 15, ty = tid >> 4;
    int row_base = blockIdx.x * 64;
    int swA = ty & 7;             // (row>>2)&7 for row=ty*4+r  == ty&7
    int swB = tx & 7;             // (col>>2)&7 for col=tx*4+c  == tx&7

    // load A tile once (coalesced 16B/lane, swizzled store: conflict-free)
    for (int idx = tid; idx < 64 * 64; idx += 256) {
        int r = idx >> 6, kv = idx & 63;
        float4 v = *(const float4*)&g_hat[(size_t)(row_base + r) * DIMK + kv * 4];
        Ash[r * 64 + (kv ^ ((r >> 2) & 7))] = v;
    }
    if (tid < 64) s_row[tid] = 0.0f;

    float racc0 = 0.f, racc1 = 0.f, racc2 = 0.f, racc3 = 0.f;

    for (int ct = 0; ct < TWO_N / 64; ct++) {
        __syncthreads();   // previous tile's compute done before overwrite (also fences s_row zero on ct==0)
        int col_base = ct * 64;
        for (int idx = tid; idx < 64 * 64; idx += 256) {
            int r = idx >> 6, kv = idx & 63;
            float4 v = *(const float4*)&g_hat[(size_t)(col_base + r) * DIMK + kv * 4];
            Bsh[r * 64 + (kv ^ ((r >> 2) & 7))] = v;
        }
        __syncthreads();

        unsigned long long acc[4][4];
        #pragma unroll
        for (int r = 0; r < 4; r++)
            #pragma unroll
            for (int c = 0; c < 4; c++) acc[r][c] = 0ull;

        #pragma unroll 2
        for (int kv = 0; kv < 64; kv++) {
            float4 a4[4], b4[4];
            int ka = kv ^ swA, kb = kv ^ swB;
            #pragma unroll
            for (int r = 0; r < 4; r++) a4[r] = Ash[(ty * 4 + r) * 64 + ka];
            #pragma unroll
            for (int c = 0; c < 4; c++) b4[c] = Bsh[(tx * 4 + c) * 64 + kb];

            unsigned long long ap01[4], ap23[4], bp01[4], bp23[4];
            #pragma unroll
            for (int r = 0; r < 4; r++) {
                ap01[r] = pk2(a4[r].x, a4[r].y);
                ap23[r] = pk2(a4[r].z, a4[r].w);
            }
            #pragma unroll
            for (int c = 0; c < 4; c++) {
                bp01[c] = pk2(b4[c].x, b4[c].y);
                bp23[c] = pk2(b4[c].z, b4[c].w);
            }
            #pragma unroll
            for (int r = 0; r < 4; r++)
                #pragma unroll
                for (int c = 0; c < 4; c++) {
                    acc[r][c] = ffma2(ap01[r], bp01[c], acc[r][c]);
                    acc[r][c] = ffma2(ap23[r], bp23[c], acc[r][c]);
                }
        }

        // epilogue: sim -> exp(2*sim), mask self-diagonal, row-accumulate
        float er[4] = {0.f, 0.f, 0.f, 0.f};
        #pragma unroll
        for (int r = 0; r < 4; r++) {
            int gr = row_base + ty * 4 + r;
            #pragma unroll
            for (int c = 0; c < 4; c++) {
                float2 s2 = unpk2(acc[r][c]);
                float sim = s2.x + s2.y;
                float e = __expf(sim * INV_TEMP);
                int gc = col_base + tx * 4 + c;
                if (gr == gc) e = 0.0f;
                er[r] += e;
            }
        }
        racc0 += er[0]; racc1 += er[1]; racc2 += er[2]; racc3 += er[3];
    }

    atomicAdd(&s_row[ty * 4 + 0], racc0);
    atomicAdd(&s_row[ty * 4 + 1], racc1);
    atomicAdd(&s_row[ty * 4 + 2], racc2);
    atomicAdd(&s_row[ty * 4 + 3], racc3);
    __syncthreads();
    if (tid < 64) g_rowsum[row_base + tid] = s_row[tid];
}

// ---------------- kernel 4: final reduction to scalar ----------------
__global__ void ntx_finalize(float* __restrict__ out) {
    __shared__ float sh[256];
    int tid = threadIdx.x;
    float acc = 0.f;
    for (int i = tid; i < TWO_N; i += 256)
        acc += logf(g_rowsum[i]) - INV_TEMP * g_pos[i];
    sh[tid] = acc;
    __syncthreads();
    for (int s = 128; s >= 1; s >>= 1) {
        if (tid < s) sh[tid] += sh[tid + s];
        __syncthreads();
    }
    if (tid == 0) out[0] = sh[0] / (float)TWO_N;
}

extern "C" void kernel_launch(void* const* d_in, const int* in_sizes, int n_in,
                              void* d_out, int out_size) {
    const float* zis = (const float*)d_in[0];
    const float* zjs = (const float*)d_in[1];
    float* out = (float*)d_out;
    (void)in_sizes; (void)n_in; (void)out_size;

    const size_t smem = 2 * 64 * 64 * sizeof(float4);  // 128 KB
    cudaFuncSetAttribute(ntx_main, cudaFuncAttributeMaxDynamicSharedMemorySize,
                         (int)smem);

    ntx_normalize<<<TWO_N / 8, dim3(32, 8)>>>(zis, zjs);
    ntx_pos<<<TWO_N / 8, dim3(32, 8)>>>();
    ntx_main<<<TWO_N / 64, 256, smem>>>();
    ntx_finalize<<<1, 256>>>(out);
}

// round 5
// speedup vs baseline: 8.1945x; 8.1945x over previous
#include <cuda_runtime.h>
#include <cuda_fp16.h>
#include <math.h>

#define NBATCH 4096
#define TWO_N  8192
#define DIMK   256
#define INV_TEMP 2.0f

// ---------------- device scratch (no allocs allowed) ----------------
__device__ __half g_half[TWO_N * DIMK];     // normalized reps fp16 (4 MB)
__device__ float  g_pos[TWO_N];             // positive-pair cosine (fp32 exact)
__device__ float  g_rowsumH[2 * TWO_N];     // per-column-half row sums
__device__ float  g_partial[32];            // finalize partials

// ---------------- PTX helpers (base sm_103 target only!) ----------------
static __device__ __forceinline__ unsigned smem_u32(const void* p) {
    unsigned a;
    asm("{ .reg .u64 t; cvta.to.shared.u64 t, %1; cvt.u32.u64 %0, t; }" : "=r"(a) : "l"(p));
    return a;
}

#define CP_ASYNC16(dst, src) \
    asm volatile("cp.async.cg.shared.global [%0], [%1], 16;" :: "r"(dst), "l"(src) : "memory")
#define CP_ASYNC_COMMIT() asm volatile("cp.async.commit_group;" ::: "memory")
#define CP_ASYNC_WAIT0()  asm volatile("cp.async.wait_group 0;" ::: "memory")

#define LDSM_X4(r0, r1, r2, r3, addr) \
    asm volatile("ldmatrix.sync.aligned.m8n8.x4.shared.b16 {%0,%1,%2,%3}, [%4];" \
        : "=r"(r0), "=r"(r1), "=r"(r2), "=r"(r3) : "r"(addr))

#define MMA16816(c0, c1, c2, c3, a0, a1, a2, a3, b0, b1) \
    asm volatile("mma.sync.aligned.m16n8k16.row.col.f32.f16.f16.f32 " \
        "{%0,%1,%2,%3}, {%4,%5,%6,%7}, {%8,%9}, {%0,%1,%2,%3};" \
        : "+f"(c0), "+f"(c1), "+f"(c2), "+f"(c3) \
        : "r"(a0), "r"(a1), "r"(a2), "r"(a3), "r"(b0), "r"(b1))

// ---------------- kernel 1: normalize + positive pairs ----------------
// reps row p = zjs[p], row p+N = zis[p]; one warp per pair
__global__ void ntx_norm(const float* __restrict__ zis,
                         const float* __restrict__ zjs) {
    int p    = blockIdx.x * 8 + (threadIdx.x >> 5);
    int lane = threadIdx.x & 31;
    const float4* j4 = (const float4*)(zjs + (size_t)p * DIMK);
    const float4* i4 = (const float4*)(zis + (size_t)p * DIMK);
    float4 ja = j4[lane], jb = j4[lane + 32];
    float4 ia = i4[lane], ib = i4[lane + 32];
    float ssj = ja.x*ja.x+ja.y*ja.y+ja.z*ja.z+ja.w*ja.w + jb.x*jb.x+jb.y*jb.y+jb.z*jb.z+jb.w*jb.w;
    float ssi = ia.x*ia.x+ia.y*ia.y+ia.z*ia.z+ia.w*ia.w + ib.x*ib.x+ib.y*ib.y+ib.z*ib.z+ib.w*ib.w;
    float dot = ja.x*ia.x+ja.y*ia.y+ja.z*ia.z+ja.w*ia.w + jb.x*ib.x+jb.y*ib.y+jb.z*ib.z+jb.w*ib.w;
    #pragma unroll
    for (int o = 16; o >= 1; o >>= 1) {
        ssj += __shfl_xor_sync(0xFFFFFFFFu, ssj, o);
        ssi += __shfl_xor_sync(0xFFFFFFFFu, ssi, o);
        dot += __shfl_xor_sync(0xFFFFFFFFu, dot, o);
    }
    float rnj = rsqrtf(ssj), rni = rsqrtf(ssi);
    __half2* hj = (__half2*)(g_half + (size_t)p * DIMK) + lane * 4;
    __half2* hi = (__half2*)(g_half + (size_t)(p + NBATCH) * DIMK) + lane * 4;
    hj[0] = __floats2half2_rn(ja.x*rnj, ja.y*rnj);
    hj[1] = __floats2half2_rn(ja.z*rnj, ja.w*rnj);
    hj[2] = __floats2half2_rn(jb.x*rnj, jb.y*rnj);
    hj[3] = __floats2half2_rn(jb.z*rnj, jb.w*rnj);
    hi[0] = __floats2half2_rn(ia.x*rni, ia.y*rni);
    hi[1] = __floats2half2_rn(ia.z*rni, ia.w*rni);
    hi[2] = __floats2half2_rn(ib.x*rni, ib.y*rni);
    hi[3] = __floats2half2_rn(ib.z*rni, ib.w*rni);
    if (lane == 0) {
        float pos = dot * rnj * rni;
        g_pos[p] = pos;
        g_pos[p + NBATCH] = pos;
    }
}

// ---------------- kernel 2: HMMA Gram + exp + row-sum ----------------
// grid 128: r = bx>>1 (128-row tile), h = bx&1 (4096-col half).
// SMEM: A 128x256 fp16 (swizzled, persistent) + B double-buffered.
// 8 warps = 2(m) x 4(n); warp tile 64x32; accumulators in registers.
#define SMA   0
#define SMB   65536
#define BBUF  65536
#define SMEM_TOTAL (65536 + 2 * BBUF)

__global__ void __launch_bounds__(256, 1) ntx_main() {
    extern __shared__ char smem[];
    unsigned sb = smem_u32(smem);
    __shared__ float s_row[128];

    int tid = threadIdx.x, wid = tid >> 5, lane = tid & 31;
    int r = blockIdx.x >> 1, h = blockIdx.x & 1;
    int row_base = r * 128, col0 = h * 4096;

    int wm = (wid & 1) * 64;          // warp row offset
    int wn = (wid >> 1) * 32;         // warp col offset
    int trow  = lane >> 2;            // 0..7 fragment row
    int tcol2 = lane & 3;             // frag col pair

    // ldmatrix per-thread addressing: rowin within 16-row group, k-block
    int rowin = ((lane >> 3) & 1) * 8 + (lane & 7);
    int kb    = lane >> 4;            // 0/1 -> k 0-7 / 8-15
    int sw    = lane & 7;             // swizzle key (rowin & 7)

    if (tid < 128) s_row[tid] = 0.0f;

    // ---- load A tile (128 rows x 512 B), swizzled ----
    const char* Ag = (const char*)g_half + (size_t)row_base * 512;
    #pragma unroll
    for (int i = 0; i < 16; i++) {
        int idx = tid + i * 256;
        int row = idx >> 5, u = idx & 31;
        CP_ASYNC16(sb + SMA + row * 512 + ((u ^ (row & 7)) << 4),
                   Ag + (size_t)row * 512 + u * 16);
    }
    // ---- load B tile 0 ----
    const char* Bg0 = (const char*)g_half + (size_t)col0 * 512;
    #pragma unroll
    for (int i = 0; i < 16; i++) {
        int idx = tid + i * 256;
        int row = idx >> 5, u = idx & 31;
        CP_ASYNC16(sb + SMB + row * 512 + ((u ^ (row & 7)) << 4),
                   Bg0 + (size_t)row * 512 + u * 16);
    }
    CP_ASYNC_COMMIT();
    CP_ASYNC_WAIT0();
    __syncthreads();

    // precomputed byte offsets
    unsigned abyte[4], bbyte[2];
    #pragma unroll
    for (int mt = 0; mt < 4; mt++) abyte[mt] = (unsigned)((wm + mt * 16 + rowin) * 512);
    #pragma unroll
    for (int ng = 0; ng < 2; ng++)  bbyte[ng] = (unsigned)((wn + ng * 16 + rowin) * 512);

    float rsum[4][2];
    #pragma unroll
    for (int mt = 0; mt < 4; mt++) { rsum[mt][0] = 0.f; rsum[mt][1] = 0.f; }

    for (int ct = 0; ct < 32; ct++) {
        unsigned curB = sb + SMB + (unsigned)(ct & 1) * BBUF;

        // prefetch next B tile into the other buffer
        if (ct + 1 < 32) {
            unsigned nxtB = sb + SMB + (unsigned)((ct + 1) & 1) * BBUF;
            const char* Bg = (const char*)g_half + (size_t)(col0 + (ct + 1) * 128) * 512;
            #pragma unroll
            for (int i = 0; i < 16; i++) {
                int idx = tid + i * 256;
                int row = idx >> 5, u = idx & 31;
                CP_ASYNC16(nxtB + row * 512 + ((u ^ (row & 7)) << 4),
                           Bg + (size_t)row * 512 + u * 16);
            }
            CP_ASYNC_COMMIT();
        }

        float acc[4][4][4];
        #pragma unroll
        for (int mt = 0; mt < 4; mt++)
            #pragma unroll
            for (int nt = 0; nt < 4; nt++)
                #pragma unroll
                for (int e = 0; e < 4; e++) acc[mt][nt][e] = 0.f;

        #pragma unroll 4
        for (int ks = 0; ks < 16; ks++) {
            unsigned koff = (unsigned)(((ks * 2 + kb) ^ sw) << 4);
            unsigned a0[4], a1[4], a2[4], a3[4];
            #pragma unroll
            for (int mt = 0; mt < 4; mt++)
                LDSM_X4(a0[mt], a1[mt], a2[mt], a3[mt], sb + SMA + abyte[mt] + koff);
            unsigned b0[2], b1[2], b2[2], b3[2];
            #pragma unroll
            for (int ng = 0; ng < 2; ng++)
                LDSM_X4(b0[ng], b1[ng], b2[ng], b3[ng], curB + bbyte[ng] + koff);

            #pragma unroll
            for (int mt = 0; mt < 4; mt++) {
                MMA16816(acc[mt][0][0], acc[mt][0][1], acc[mt][0][2], acc[mt][0][3],
                         a0[mt], a1[mt], a2[mt], a3[mt], b0[0], b2[0]);
                MMA16816(acc[mt][1][0], acc[mt][1][1], acc[mt][1][2], acc[mt][1][3],
                         a0[mt], a1[mt], a2[mt], a3[mt], b1[0], b3[0]);
                MMA16816(acc[mt][2][0], acc[mt][2][1], acc[mt][2][2], acc[mt][2][3],
                         a0[mt], a1[mt], a2[mt], a3[mt], b0[1], b2[1]);
                MMA16816(acc[mt][3][0], acc[mt][3][1], acc[mt][3][2], acc[mt][3][3],
                         a0[mt], a1[mt], a2[mt], a3[mt], b1[1], b3[1]);
            }
        }

        // epilogue: exp(2*sim), mask self-diagonal, accumulate row sums
        bool diag = (row_base == col0 + ct * 128);
        #pragma unroll
        for (int mt = 0; mt < 4; mt++) {
            #pragma unroll
            for (int nt = 0; nt < 4; nt++) {
                int c0 = wn + nt * 8 + tcol2 * 2;
                int r0 = wm + mt * 16 + trow;
                float e00 = __expf(INV_TEMP * acc[mt][nt][0]);
                float e01 = __expf(INV_TEMP * acc[mt][nt][1]);
                float e10 = __expf(INV_TEMP * acc[mt][nt][2]);
                float e11 = __expf(INV_TEMP * acc[mt][nt][3]);
                if (diag) {
                    if (r0 == c0)         e00 = 0.f;
                    if (r0 == c0 + 1)     e01 = 0.f;
                    if (r0 + 8 == c0)     e10 = 0.f;
                    if (r0 + 8 == c0 + 1) e11 = 0.f;
                }
                rsum[mt][0] += e00 + e01;
                rsum[mt][1] += e10 + e11;
            }
        }

        CP_ASYNC_WAIT0();
        __syncthreads();
    }

    // reduce 4 lanes sharing a row, then across the 4 n-warps via smem atomics
    #pragma unroll
    for (int mt = 0; mt < 4; mt++) {
        #pragma unroll
        for (int hf = 0; hf < 2; hf++) {
            float v = rsum[mt][hf];
            v += __shfl_xor_sync(0xFFFFFFFFu, v, 1);
            v += __shfl_xor_sync(0xFFFFFFFFu, v, 2);
            if ((lane & 3) == 0)
                atomicAdd(&s_row[wm + mt * 16 + hf * 8 + trow], v);
        }
    }
    __syncthreads();
    if (tid < 128)
        g_rowsumH[h * TWO_N + row_base + tid] = s_row[tid];
}

// ---------------- kernel 3: per-row loss partials ----------------
__global__ void ntx_fin1() {
    __shared__ float sh[256];
    int tid = threadIdx.x;
    int i = blockIdx.x * 256 + tid;
    float rs = g_rowsumH[i] + g_rowsumH[TWO_N + i];
    sh[tid] = logf(rs) - INV_TEMP * g_pos[i];
    __syncthreads();
    for (int s = 128; s >= 1; s >>= 1) {
        if (tid < s) sh[tid] += sh[tid + s];
        __syncthreads();
    }
    if (tid == 0) g_partial[blockIdx.x] = sh[0];
}

// ---------------- kernel 4: final scalar ----------------
__global__ void ntx_fin2(float* __restrict__ out) {
    int lane = threadIdx.x;
    float v = g_partial[lane];
    #pragma unroll
    for (int o = 16; o >= 1; o >>= 1) v += __shfl_xor_sync(0xFFFFFFFFu, v, o);
    if (lane == 0) out[0] = v / (float)TWO_N;
}

extern "C" void kernel_launch(void* const* d_in, const int* in_sizes, int n_in,
                              void* d_out, int out_size) {
    const float* zis = (const float*)d_in[0];
    const float* zjs = (const float*)d_in[1];
    float* out = (float*)d_out;
    (void)in_sizes; (void)n_in; (void)out_size;

    cudaFuncSetAttribute(ntx_main, cudaFuncAttributeMaxDynamicSharedMemorySize,
                         SMEM_TOTAL);

    ntx_norm<<<NBATCH / 8, 256>>>(zis, zjs);
    ntx_main<<<128, 256, SMEM_TOTAL>>>();
    ntx_fin1<<<TWO_N / 256, 256>>>();
    ntx_fin2<<<1, 32>>>(out);
}

// round 7
// speedup vs baseline: 13.0275x; 1.5898x over previous
#include <cuda_runtime.h>
#include <cuda_fp16.h>
#include <math.h>

#define NBATCH 4096
#define TWO_N  8192
#define DIMK   256
#define INV_TEMP 2.0f

// ---------------- device scratch (no allocs allowed) ----------------
__device__ __half g_half[TWO_N * DIMK];       // normalized reps fp16 (4 MB)
__device__ float  g_pos[TWO_N];               // positive-pair cosine (fp32 exact)
__device__ float  g_scatter[64 * TWO_N];      // per-(row, key) partial sums (2 MB)
__device__ float  g_partial[32];              // finalize partials

// ---------------- PTX helpers (base sm_103 target only) ----------------
static __device__ __forceinline__ unsigned smem_u32(const void* p) {
    unsigned a;
    asm("{ .reg .u64 t; cvta.to.shared.u64 t, %1; cvt.u32.u64 %0, t; }" : "=r"(a) : "l"(p));
    return a;
}

#define CP_ASYNC16(dst, src) \
    asm volatile("cp.async.cg.shared.global [%0], [%1], 16;" :: "r"(dst), "l"(src) : "memory")
#define CP_ASYNC_COMMIT() asm volatile("cp.async.commit_group;" ::: "memory")

#define LDSM_X4(r0, r1, r2, r3, addr) \
    asm volatile("ldmatrix.sync.aligned.m8n8.x4.shared.b16 {%0,%1,%2,%3}, [%4];" \
        : "=r"(r0), "=r"(r1), "=r"(r2), "=r"(r3) : "r"(addr))

#define MMA16816(c0, c1, c2, c3, a0, a1, a2, a3, b0, b1) \
    asm volatile("mma.sync.aligned.m16n8k16.row.col.f32.f16.f16.f32 " \
        "{%0,%1,%2,%3}, {%4,%5,%6,%7}, {%8,%9}, {%0,%1,%2,%3};" \
        : "+f"(c0), "+f"(c1), "+f"(c2), "+f"(c3) \
        : "r"(a0), "r"(a1), "r"(a2), "r"(a3), "r"(b0), "r"(b1))

// ---------------- kernel 1: normalize + positive pairs ----------------
__global__ void ntx_norm(const float* __restrict__ zis,
                         const float* __restrict__ zjs) {
    int p    = blockIdx.x * 8 + (threadIdx.x >> 5);
    int lane = threadIdx.x & 31;
    const float4* j4 = (const float4*)(zjs + (size_t)p * DIMK);
    const float4* i4 = (const float4*)(zis + (size_t)p * DIMK);
    float4 ja = j4[lane], jb = j4[lane + 32];
    float4 ia = i4[lane], ib = i4[lane + 32];
    float ssj = ja.x*ja.x+ja.y*ja.y+ja.z*ja.z+ja.w*ja.w + jb.x*jb.x+jb.y*jb.y+jb.z*jb.z+jb.w*jb.w;
    float ssi = ia.x*ia.x+ia.y*ia.y+ia.z*ia.z+ia.w*ia.w + ib.x*ib.x+ib.y*ib.y+ib.z*ib.z+ib.w*ib.w;
    float dot = ja.x*ia.x+ja.y*ia.y+ja.z*ia.z+ja.w*ia.w + jb.x*ib.x+jb.y*ib.y+jb.z*ib.z+jb.w*ib.w;
    #pragma unroll
    for (int o = 16; o >= 1; o >>= 1) {
        ssj += __shfl_xor_sync(0xFFFFFFFFu, ssj, o);
        ssi += __shfl_xor_sync(0xFFFFFFFFu, ssi, o);
        dot += __shfl_xor_sync(0xFFFFFFFFu, dot, o);
    }
    float rnj = rsqrtf(ssj), rni = rsqrtf(ssi);
    __half2* hj = (__half2*)(g_half + (size_t)p * DIMK) + lane * 4;
    __half2* hi = (__half2*)(g_half + (size_t)(p + NBATCH) * DIMK) + lane * 4;
    hj[0] = __floats2half2_rn(ja.x*rnj, ja.y*rnj);
    hj[1] = __floats2half2_rn(ja.z*rnj, ja.w*rnj);
    hj[2] = __floats2half2_rn(jb.x*rnj, jb.y*rnj);
    hj[3] = __floats2half2_rn(jb.z*rnj, jb.w*rnj);
    hi[0] = __floats2half2_rn(ia.x*rni, ia.y*rni);
    hi[1] = __floats2half2_rn(ia.z*rni, ia.w*rni);
    hi[2] = __floats2half2_rn(ib.x*rni, ib.y*rni);
    hi[3] = __floats2half2_rn(ib.z*rni, ib.w*rni);
    if (lane == 0) {
        float pos = dot * rnj * rni;
        g_pos[p] = pos;
        g_pos[p + NBATCH] = pos;
    }
}

// ---------------- kernel 2: symmetric HMMA Gram + exp + row/col sums ----
// Upper-triangle tiles only (2080 of 4096). 32 band-pairs (p, 63-p) of 65
// tiles, 4 blocks each -> grid 128. Tile (I,J): row-sums -> scatter key J,
// col-sums -> scatter key I (I!=J). Every row gets exactly 64 keyed slots.
#define SMI   0
#define SMJ   65536
#define BBUF  65536
#define SMEM_TOTAL (65536 + 2 * BBUF)

static __device__ __forceinline__ void map_ij(int g, int p, int n1, int& I, int& J) {
    if (g < n1) { I = p;      J = p + g; }
    else        { I = 63 - p; J = 63 - p + (g - n1); }
}

static __device__ __forceinline__ void load_tile(unsigned dstbase, int band, int tid) {
    const char* src = (const char*)g_half + (size_t)band * 128 * 512;
    #pragma unroll
    for (int i = 0; i < 16; i++) {
        int idx = tid + i * 256;
        int row = idx >> 5, u = idx & 31;
        CP_ASYNC16(dstbase + row * 512 + ((u ^ (row & 7)) << 4),
                   src + (size_t)row * 512 + u * 16);
    }
}

__global__ void __launch_bounds__(256, 1) ntx_main() {
    extern __shared__ char smem[];
    unsigned sb = smem_u32(smem);
    __shared__ float s_roww[4][128];   // per n-warp-group row partials
    __shared__ float s_colw[2][128];   // per m-warp-group col partials

    int tid = threadIdx.x, wid = tid >> 5, lane = tid & 31;
    int p = blockIdx.x >> 2, q = blockIdx.x & 3;
    int g0 = (q == 0) ? 0 : q * 16 + 1;
    int L  = (q == 0) ? 17 : 16;
    int n1 = 64 - p;

    int wm = (wid & 1) * 64;
    int wn = (wid >> 1) * 32;
    int trow  = lane >> 2;
    int tcol2 = lane & 3;
    int rowin = ((lane >> 3) & 1) * 8 + (lane & 7);
    int kb    = lane >> 4;
    int sw    = lane & 7;

    unsigned abyte[4], bbyte[2];
    #pragma unroll
    for (int mt = 0; mt < 4; mt++) abyte[mt] = (unsigned)((wm + mt * 16 + rowin) * 512);
    #pragma unroll
    for (int ng = 0; ng < 2; ng++)  bbyte[ng] = (unsigned)((wn + ng * 16 + rowin) * 512);

    // prologue: load A_I and first A_J
    int I0, J0; map_ij(g0, p, n1, I0, J0);
    load_tile(sb + SMI, I0, tid);
    load_tile(sb + SMJ, J0, tid);
    CP_ASYNC_COMMIT();
    int curI = I0;

    for (int k = 0; k < L; k++) {
        int I, J; map_ij(g0 + k, p, n1, I, J);
        if (I != curI) {                       // band switch (<=1 per block)
            load_tile(sb + SMI, I, tid);
            CP_ASYNC_COMMIT();
            curI = I;
        }
        if (k + 1 < L) {                       // prefetch next A_J
            int In, Jn; map_ij(g0 + k + 1, p, n1, In, Jn);
            load_tile(sb + SMJ + (unsigned)((k + 1) & 1) * BBUF, Jn, tid);
            CP_ASYNC_COMMIT();
            asm volatile("cp.async.wait_group 1;" ::: "memory");
        } else {
            asm volatile("cp.async.wait_group 0;" ::: "memory");
        }
        __syncthreads();                       // S1: buffers ready, prev write done

        unsigned curB = sb + SMJ + (unsigned)(k & 1) * BBUF;

        float acc[4][4][4];
        #pragma unroll
        for (int mt = 0; mt < 4; mt++)
            #pragma unroll
            for (int nt = 0; nt < 4; nt++)
                #pragma unroll
                for (int e = 0; e < 4; e++) acc[mt][nt][e] = 0.f;

        #pragma unroll 4
        for (int ks = 0; ks < 16; ks++) {
            unsigned koff = (unsigned)(((ks * 2 + kb) ^ sw) << 4);
            unsigned a0[4], a1[4], a2[4], a3[4];
            #pragma unroll
            for (int mt = 0; mt < 4; mt++)
                LDSM_X4(a0[mt], a1[mt], a2[mt], a3[mt], sb + SMI + abyte[mt] + koff);
            unsigned b0[2], b1[2], b2[2], b3[2];
            #pragma unroll
            for (int ng = 0; ng < 2; ng++)
                LDSM_X4(b0[ng], b1[ng], b2[ng], b3[ng], curB + bbyte[ng] + koff);
            #pragma unroll
            for (int mt = 0; mt < 4; mt++) {
                MMA16816(acc[mt][0][0], acc[mt][0][1], acc[mt][0][2], acc[mt][0][3],
                         a0[mt], a1[mt], a2[mt], a3[mt], b0[0], b2[0]);
                MMA16816(acc[mt][1][0], acc[mt][1][1], acc[mt][1][2], acc[mt][1][3],
                         a0[mt], a1[mt], a2[mt], a3[mt], b1[0], b3[0]);
                MMA16816(acc[mt][2][0], acc[mt][2][1], acc[mt][2][2], acc[mt][2][3],
                         a0[mt], a1[mt], a2[mt], a3[mt], b0[1], b2[1]);
                MMA16816(acc[mt][3][0], acc[mt][3][1], acc[mt][3][2], acc[mt][3][3],
                         a0[mt], a1[mt], a2[mt], a3[mt], b1[1], b3[1]);
            }
        }

        // epilogue: exp(2*sim), mask self-diagonal, row + col partials
        bool diag = (I == J);
        float rsum[4][2], csum[4][2];
        #pragma unroll
        for (int x = 0; x < 4; x++) { rsum[x][0]=rsum[x][1]=csum[x][0]=csum[x][1]=0.f; }
        #pragma unroll
        for (int mt = 0; mt < 4; mt++) {
            int r0 = wm + mt * 16 + trow;
            #pragma unroll
            for (int nt = 0; nt < 4; nt++) {
                int c0 = wn + nt * 8 + tcol2 * 2;
                float e00 = __expf(INV_TEMP * acc[mt][nt][0]);
                float e01 = __expf(INV_TEMP * acc[mt][nt][1]);
                float e10 = __expf(INV_TEMP * acc[mt][nt][2]);
                float e11 = __expf(INV_TEMP * acc[mt][nt][3]);
                if (diag) {
                    if (r0 == c0)         e00 = 0.f;
                    if (r0 == c0 + 1)     e01 = 0.f;
                    if (r0 + 8 == c0)     e10 = 0.f;
                    if (r0 + 8 == c0 + 1) e11 = 0.f;
                }
                rsum[mt][0] += e00 + e01;
                rsum[mt][1] += e10 + e11;
                csum[nt][0] += e00 + e10;
                csum[nt][1] += e01 + e11;
            }
        }
        // row partials: reduce 4 lanes sharing a row -> plain store per n-group
        #pragma unroll
        for (int mt = 0; mt < 4; mt++)
            #pragma unroll
            for (int hf = 0; hf < 2; hf++) {
                float v = rsum[mt][hf];
                v += __shfl_xor_sync(0xFFFFFFFFu, v, 1);
                v += __shfl_xor_sync(0xFFFFFFFFu, v, 2);
                if ((lane & 3) == 0)
                    s_roww[wid >> 1][wm + mt * 16 + hf * 8 + trow] = v;
            }
        // col partials: reduce 8 lanes sharing a col -> plain store per m-group
        #pragma unroll
        for (int nt = 0; nt < 4; nt++)
            #pragma unroll
            for (int j = 0; j < 2; j++) {
                float v = csum[nt][j];
                v += __shfl_xor_sync(0xFFFFFFFFu, v, 4);
                v += __shfl_xor_sync(0xFFFFFFFFu, v, 8);
                v += __shfl_xor_sync(0xFFFFFFFFu, v, 16);
                if (lane < 4)
                    s_colw[wid & 1][wn + nt * 8 + lane * 2 + j] = v;
            }
        __syncthreads();                       // S3: partials complete

        if (tid < 128) {
            float rv = s_roww[0][tid] + s_roww[1][tid] + s_roww[2][tid] + s_roww[3][tid];
            g_scatter[(size_t)J * TWO_N + I * 128 + tid] = rv;
            if (!diag) {
                float cv = s_colw[0][tid] + s_colw[1][tid];
                g_scatter[(size_t)I * TWO_N + J * 128 + tid] = cv;
            }
        }
    }
}

// ---------------- kernel 3: per-row loss partials ----------------
__global__ void ntx_fin1() {
    __shared__ float sh[256];
    int tid = threadIdx.x;
    int i = blockIdx.x * 256 + tid;
    float rs = 0.f;
    #pragma unroll
    for (int k = 0; k < 64; k++) rs += g_scatter[(size_t)k * TWO_N + i];
    sh[tid] = logf(rs) - INV_TEMP * g_pos[i];
    __syncthreads();
    for (int s = 128; s >= 1; s >>= 1) {
        if (tid < s) sh[tid] += sh[tid + s];
        __syncthreads();
    }
    if (tid == 0) g_partial[blockIdx.x] = sh[0];
}

// ---------------- kernel 4: final scalar ----------------
__global__ void ntx_fin2(float* __restrict__ out) {
    int lane = threadIdx.x;
    float v = g_partial[lane];
    #pragma unroll
    for (int o = 16; o >= 1; o >>= 1) v += __shfl_xor_sync(0xFFFFFFFFu, v, o);
    if (lane == 0) out[0] = v / (float)TWO_N;
}

extern "C" void kernel_launch(void* const* d_in, const int* in_sizes, int n_in,
                              void* d_out, int out_size) {
    const float* zis = (const float*)d_in[0];
    const float* zjs = (const float*)d_in[1];
    float* out = (float*)d_out;
    (void)in_sizes; (void)n_in; (void)out_size;

    cudaFuncSetAttribute(ntx_main, cudaFuncAttributeMaxDynamicSharedMemorySize,
                         SMEM_TOTAL);

    ntx_norm<<<NBATCH / 8, 256>>>(zis, zjs);
    ntx_main<<<128, 256, SMEM_TOTAL>>>();
    ntx_fin1<<<32, 256>>>();
    ntx_fin2<<<1, 32>>>(out);
}

// round 8
// speedup vs baseline: 13.2982x; 1.0208x over previous
#include <cuda_runtime.h>
#include <cuda_fp16.h>
#include <math.h>

#define NBATCH 4096
#define TWO_N  8192
#define DIMK   256
#define INV_TEMP 2.0f
#define QSCALE 16.0f            // fp8 quantization scale
#define EPSCL  (2.0f / 256.0f)  // epilogue: INV_TEMP / QSCALE^2

// ---------------- device scratch (no allocs allowed) ----------------
__device__ unsigned char g_fp8[TWO_N * DIMK]; // normalized reps e4m3*16 (2 MB)
__device__ float  g_pos[TWO_N];               // positive-pair cosine (fp32 exact)
__device__ float  g_scatter[64 * TWO_N];      // per-(row, key) partial sums (2 MB)
__device__ float  g_partial[32];              // finalize partials

// ---------------- PTX helpers (base sm_103 target only) ----------------
static __device__ __forceinline__ unsigned smem_u32(const void* p) {
    unsigned a;
    asm("{ .reg .u64 t; cvta.to.shared.u64 t, %1; cvt.u32.u64 %0, t; }" : "=r"(a) : "l"(p));
    return a;
}

// pack two f32 -> e4m3x2 (lo in low byte)
static __device__ __forceinline__ unsigned short pk_e4m3(float lo, float hi) {
    unsigned short r;
    asm("cvt.rn.satfinite.e4m3x2.f32 %0, %2, %1;" : "=h"(r) : "f"(lo), "f"(hi));
    return r;
}

#define CP_ASYNC16(dst, src) \
    asm volatile("cp.async.cg.shared.global [%0], [%1], 16;" :: "r"(dst), "l"(src) : "memory")
#define CP_ASYNC_COMMIT() asm volatile("cp.async.commit_group;" ::: "memory")

#define LDSM_X4(r0, r1, r2, r3, addr) \
    asm volatile("ldmatrix.sync.aligned.m8n8.x4.shared.b16 {%0,%1,%2,%3}, [%4];" \
        : "=r"(r0), "=r"(r1), "=r"(r2), "=r"(r3) : "r"(addr))

// fp8 e4m3 MMA: m16n8k32, fp32 accumulate
#define MMA_FP8(c0, c1, c2, c3, a0, a1, a2, a3, b0, b1) \
    asm volatile("mma.sync.aligned.m16n8k32.row.col.f32.e4m3.e4m3.f32 " \
        "{%0,%1,%2,%3}, {%4,%5,%6,%7}, {%8,%9}, {%0,%1,%2,%3};" \
        : "+f"(c0), "+f"(c1), "+f"(c2), "+f"(c3) \
        : "r"(a0), "r"(a1), "r"(a2), "r"(a3), "r"(b0), "r"(b1))

// ---------------- kernel 1: normalize + positive pairs -> fp8 ----------------
__global__ void ntx_norm(const float* __restrict__ zis,
                         const float* __restrict__ zjs) {
    int p    = blockIdx.x * 8 + (threadIdx.x >> 5);
    int lane = threadIdx.x & 31;
    const float4* j4 = (const float4*)(zjs + (size_t)p * DIMK);
    const float4* i4 = (const float4*)(zis + (size_t)p * DIMK);
    float4 ja = j4[lane], jb = j4[lane + 32];
    float4 ia = i4[lane], ib = i4[lane + 32];
    float ssj = ja.x*ja.x+ja.y*ja.y+ja.z*ja.z+ja.w*ja.w + jb.x*jb.x+jb.y*jb.y+jb.z*jb.z+jb.w*jb.w;
    float ssi = ia.x*ia.x+ia.y*ia.y+ia.z*ia.z+ia.w*ia.w + ib.x*ib.x+ib.y*ib.y+ib.z*ib.z+ib.w*ib.w;
    float dot = ja.x*ia.x+ja.y*ia.y+ja.z*ia.z+ja.w*ia.w + jb.x*ib.x+jb.y*ib.y+jb.z*ib.z+jb.w*ib.w;
    #pragma unroll
    for (int o = 16; o >= 1; o >>= 1) {
        ssj += __shfl_xor_sync(0xFFFFFFFFu, ssj, o);
        ssi += __shfl_xor_sync(0xFFFFFFFFu, ssi, o);
        dot += __shfl_xor_sync(0xFFFFFFFFu, dot, o);
    }
    float rnj = rsqrtf(ssj) * QSCALE, rni = rsqrtf(ssi) * QSCALE;
    unsigned* dj = (unsigned*)(g_fp8 + (size_t)p * DIMK);
    unsigned* di = (unsigned*)(g_fp8 + (size_t)(p + NBATCH) * DIMK);
    dj[lane]      = (unsigned)pk_e4m3(ja.x*rnj, ja.y*rnj) | ((unsigned)pk_e4m3(ja.z*rnj, ja.w*rnj) << 16);
    dj[lane + 32] = (unsigned)pk_e4m3(jb.x*rnj, jb.y*rnj) | ((unsigned)pk_e4m3(jb.z*rnj, jb.w*rnj) << 16);
    di[lane]      = (unsigned)pk_e4m3(ia.x*rni, ia.y*rni) | ((unsigned)pk_e4m3(ia.z*rni, ia.w*rni) << 16);
    di[lane + 32] = (unsigned)pk_e4m3(ib.x*rni, ib.y*rni) | ((unsigned)pk_e4m3(ib.z*rni, ib.w*rni) << 16);
    if (lane == 0) {
        float pos = dot * rsqrtf(ssj) * rsqrtf(ssi);
        g_pos[p] = pos;
        g_pos[p + NBATCH] = pos;
    }
}

// ---------------- kernel 2: symmetric FP8 MMA Gram + exp + row/col sums ----
// Upper-triangle tiles (2080). 32 band-pairs (p, 63-p) of 65 tiles, 4 blocks
// each -> grid 128. Tile (I,J): row-sums -> key J, col-sums -> key I (I!=J).
// Tile = 128 rows x 256 B fp8; SMEM: A 32KB + double-buffered J 2x32KB.
#define SMI   0
#define SMJ   32768
#define BBUF  32768
#define SMEM_TOTAL (32768 * 3)

static __device__ __forceinline__ void map_ij(int g, int p, int n1, int& I, int& J) {
    if (g < n1) { I = p;      J = p + g; }
    else        { I = 63 - p; J = 63 - p + (g - n1); }
}

static __device__ __forceinline__ void load_tile(unsigned dstbase, int band, int tid) {
    const char* src = (const char*)g_fp8 + (size_t)band * 128 * 256;
    #pragma unroll
    for (int i = 0; i < 8; i++) {
        int idx = tid + i * 256;
        int row = idx >> 4, u = idx & 15;
        CP_ASYNC16(dstbase + row * 256 + ((u ^ (row & 7)) << 4),
                   src + (size_t)row * 256 + u * 16);
    }
}

__global__ void __launch_bounds__(256, 1) ntx_main() {
    extern __shared__ char smem[];
    unsigned sb = smem_u32(smem);
    __shared__ float s_roww[4][128];
    __shared__ float s_colw[2][128];

    int tid = threadIdx.x, wid = tid >> 5, lane = tid & 31;
    int p = blockIdx.x >> 2, q = blockIdx.x & 3;
    int g0 = (q == 0) ? 0 : q * 16 + 1;
    int L  = (q == 0) ? 17 : 16;
    int n1 = 64 - p;

    int wm = (wid & 1) * 64;
    int wn = (wid >> 1) * 32;
    int trow  = lane >> 2;
    int tcol2 = lane & 3;
    int sw    = lane & 7;
    // A-frag ldmatrix lane mapping: groups {rows0-7,rows8-15} x {k-lo,k-hi}
    int rowinA = ((lane >> 3) & 1) * 8 + (lane & 7);
    int kbA    = lane >> 4;
    // B-frag mapping: groups {cols0-7 k-lo, cols0-7 k-hi, cols8-15 k-lo, cols8-15 k-hi}
    int rowinB = (lane >> 4) * 8 + (lane & 7);
    int kbB    = (lane >> 3) & 1;

    unsigned abyte[4], bbyte[2];
    #pragma unroll
    for (int mt = 0; mt < 4; mt++) abyte[mt] = (unsigned)((wm + mt * 16 + rowinA) * 256);
    #pragma unroll
    for (int ng = 0; ng < 2; ng++)  bbyte[ng] = (unsigned)((wn + ng * 16 + rowinB) * 256);

    int I0, J0; map_ij(g0, p, n1, I0, J0);
    load_tile(sb + SMI, I0, tid);
    load_tile(sb + SMJ, J0, tid);
    CP_ASYNC_COMMIT();
    int curI = I0;

    for (int k = 0; k < L; k++) {
        int I, J; map_ij(g0 + k, p, n1, I, J);
        if (I != curI) {
            load_tile(sb + SMI, I, tid);
            CP_ASYNC_COMMIT();
            curI = I;
        }
        if (k + 1 < L) {
            int In, Jn; map_ij(g0 + k + 1, p, n1, In, Jn);
            load_tile(sb + SMJ + (unsigned)((k + 1) & 1) * BBUF, Jn, tid);
            CP_ASYNC_COMMIT();
            asm volatile("cp.async.wait_group 1;" ::: "memory");
        } else {
            asm volatile("cp.async.wait_group 0;" ::: "memory");
        }
        __syncthreads();

        unsigned curB = sb + SMJ + (unsigned)(k & 1) * BBUF;

        float acc[4][4][4];
        #pragma unroll
        for (int mt = 0; mt < 4; mt++)
            #pragma unroll
            for (int nt = 0; nt < 4; nt++)
                #pragma unroll
                for (int e = 0; e < 4; e++) acc[mt][nt][e] = 0.f;

        #pragma unroll
        for (int ks = 0; ks < 8; ks++) {
            unsigned koffA = (unsigned)(((ks * 2 + kbA) ^ sw) << 4);
            unsigned koffB = (unsigned)(((ks * 2 + kbB) ^ sw) << 4);
            unsigned a0[4], a1[4], a2[4], a3[4];
            #pragma unroll
            for (int mt = 0; mt < 4; mt++)
                LDSM_X4(a0[mt], a1[mt], a2[mt], a3[mt], sb + SMI + abyte[mt] + koffA);
            unsigned b0[2], b1[2], b2[2], b3[2];
            #pragma unroll
            for (int ng = 0; ng < 2; ng++)
                LDSM_X4(b0[ng], b1[ng], b2[ng], b3[ng], curB + bbyte[ng] + koffB);
            #pragma unroll
            for (int mt = 0; mt < 4; mt++) {
                MMA_FP8(acc[mt][0][0], acc[mt][0][1], acc[mt][0][2], acc[mt][0][3],
                        a0[mt], a1[mt], a2[mt], a3[mt], b0[0], b1[0]);
                MMA_FP8(acc[mt][1][0], acc[mt][1][1], acc[mt][1][2], acc[mt][1][3],
                        a0[mt], a1[mt], a2[mt], a3[mt], b2[0], b3[0]);
                MMA_FP8(acc[mt][2][0], acc[mt][2][1], acc[mt][2][2], acc[mt][2][3],
                        a0[mt], a1[mt], a2[mt], a3[mt], b0[1], b1[1]);
                MMA_FP8(acc[mt][3][0], acc[mt][3][1], acc[mt][3][2], acc[mt][3][3],
                        a0[mt], a1[mt], a2[mt], a3[mt], b2[1], b3[1]);
            }
        }

        // epilogue: exp(acc * 2/QSCALE^2), mask self-diagonal, row+col partials
        bool diag = (I == J);
        float rsum[4][2], csum[4][2];
        #pragma unroll
        for (int x = 0; x < 4; x++) { rsum[x][0]=rsum[x][1]=csum[x][0]=csum[x][1]=0.f; }
        #pragma unroll
        for (int mt = 0; mt < 4; mt++) {
            int r0 = wm + mt * 16 + trow;
            #pragma unroll
            for (int nt = 0; nt < 4; nt++) {
                int c0 = wn + nt * 8 + tcol2 * 2;
                float e00 = __expf(EPSCL * acc[mt][nt][0]);
                float e01 = __expf(EPSCL * acc[mt][nt][1]);
                float e10 = __expf(EPSCL * acc[mt][nt][2]);
                float e11 = __expf(EPSCL * acc[mt][nt][3]);
                if (diag) {
                    if (r0 == c0)         e00 = 0.f;
                    if (r0 == c0 + 1)     e01 = 0.f;
                    if (r0 + 8 == c0)     e10 = 0.f;
                    if (r0 + 8 == c0 + 1) e11 = 0.f;
                }
                rsum[mt][0] += e00 + e01;
                rsum[mt][1] += e10 + e11;
                csum[nt][0] += e00 + e10;
                csum[nt][1] += e01 + e11;
            }
        }
        #pragma unroll
        for (int mt = 0; mt < 4; mt++)
            #pragma unroll
            for (int hf = 0; hf < 2; hf++) {
                float v = rsum[mt][hf];
                v += __shfl_xor_sync(0xFFFFFFFFu, v, 1);
                v += __shfl_xor_sync(0xFFFFFFFFu, v, 2);
                if ((lane & 3) == 0)
                    s_roww[wid >> 1][wm + mt * 16 + hf * 8 + trow] = v;
            }
        #pragma unroll
        for (int nt = 0; nt < 4; nt++)
            #pragma unroll
            for (int j = 0; j < 2; j++) {
                float v = csum[nt][j];
                v += __shfl_xor_sync(0xFFFFFFFFu, v, 4);
                v += __shfl_xor_sync(0xFFFFFFFFu, v, 8);
                v += __shfl_xor_sync(0xFFFFFFFFu, v, 16);
                if (lane < 4)
                    s_colw[wid & 1][wn + nt * 8 + lane * 2 + j] = v;
            }
        __syncthreads();

        if (tid < 128) {
            float rv = s_roww[0][tid] + s_roww[1][tid] + s_roww[2][tid] + s_roww[3][tid];
            g_scatter[(size_t)J * TWO_N + I * 128 + tid] = rv;
            if (!diag) {
                float cv = s_colw[0][tid] + s_colw[1][tid];
                g_scatter[(size_t)I * TWO_N + J * 128 + tid] = cv;
            }
        }
    }
}

// ---------------- kernel 3: per-row loss partials ----------------
__global__ void ntx_fin1() {
    __shared__ float sh[256];
    int tid = threadIdx.x;
    int i = blockIdx.x * 256 + tid;
    float rs = 0.f;
    #pragma unroll
    for (int k = 0; k < 64; k++) rs += g_scatter[(size_t)k * TWO_N + i];
    sh[tid] = logf(rs) - INV_TEMP * g_pos[i];
    __syncthreads();
    for (int s = 128; s >= 1; s >>= 1) {
        if (tid < s) sh[tid] += sh[tid + s];
        __syncthreads();
    }
    if (tid == 0) g_partial[blockIdx.x] = sh[0];
}

// ---------------- kernel 4: final scalar ----------------
__global__ void ntx_fin2(float* __restrict__ out) {
    int lane = threadIdx.x;
    float v = g_partial[lane];
    #pragma unroll
    for (int o = 16; o >= 1; o >>= 1) v += __shfl_xor_sync(0xFFFFFFFFu, v, o);
    if (lane == 0) out[0] = v / (float)TWO_N;
}

extern "C" void kernel_launch(void* const* d_in, const int* in_sizes, int n_in,
                              void* d_out, int out_size) {
    const float* zis = (const float*)d_in[0];
    const float* zjs = (const float*)d_in[1];
    float* out = (float*)d_out;
    (void)in_sizes; (void)n_in; (void)out_size;

    cudaFuncSetAttribute(ntx_main, cudaFuncAttributeMaxDynamicSharedMemorySize,
                         SMEM_TOTAL);

    ntx_norm<<<NBATCH / 8, 256>>>(zis, zjs);
    ntx_main<<<128, 256, SMEM_TOTAL>>>();
    ntx_fin1<<<32, 256>>>();
    ntx_fin2<<<1, 32>>>(out);
}